// round 13
// baseline (speedup 1.0000x reference)
#include <cuda_runtime.h>

#define FULLMASK 0xffffffffu

__device__ __forceinline__ void axisang_rot(float x, float y, float z, float* __restrict__ R) {
    // reference: theta = sqrt(dot + 1e-8); R = I + s*K + (1-c)*K^2
    // fast-math: MUFU.RSQ / MUFU.SIN / MUFU.COS (error ~2^-21, budget 1e-3)
    float t2 = x * x + y * y + z * z + 1e-8f;
    float inv = rsqrtf(t2);
    float th = t2 * inv;            // sqrt(t2)
    float ax = x * inv, ay = y * inv, az = z * inv;
    float s = __sinf(th);
    float c = __cosf(th);
    float oc = 1.0f - c;
    float xx = ax * ax, yy = ay * ay, zz = az * az;
    float xy = ax * ay, xz = ax * az, yz = ay * az;
    R[0] = 1.0f + oc * (-zz - yy);
    R[1] = -s * az + oc * xy;
    R[2] =  s * ay + oc * xz;
    R[3] =  s * az + oc * xy;
    R[4] = 1.0f + oc * (-zz - xx);
    R[5] = -s * ax + oc * yz;
    R[6] = -s * ay + oc * xz;
    R[7] =  s * ax + oc * yz;
    R[8] = 1.0f + oc * (-yy - xx);
}

// ---------------------------------------------------------------------------
// Single fused kernel: chain -> l2ws, skts, kp, rots, bone (all 5 outputs)
// Per-warp smem (words): L[32*36] | S[32*36] | RT[32*18] | BT[32*6]
//                        = 3072 words (12.3 KB)
// 128-thread blocks, __launch_bounds__(128, 4): reg cap 128, 4 blocks/SM
// (196.6 KB smem) -> 16 warps/SM.
// Flush every 2 joints; all global stores via coalesced staging.
// Rigid inverse = [R^T | -R^T t]  (rotation chain => orthogonal).
// ---------------------------------------------------------------------------
#define LS_STRIDE 36
#define WARP_WORDS (1152 + 1152 + 576 + 192)  // 3072

__global__ void __launch_bounds__(128, 4)
fused_kernel(const float* __restrict__ pelvis, const float* __restrict__ bones,
             const float* __restrict__ rest, const int* __restrict__ idxs,
             float* __restrict__ out, int B)
{
    extern __shared__ float sm[];
    const int lane = threadIdx.x & 31;
    const int wid  = threadIdx.x >> 5;
    float* Lb = sm + wid * WARP_WORDS;
    float* Sb = Lb + 1152;
    float* RT = Sb + 1152;   // rots stage: elem-contiguous, RT[r*18+m]
    float* BT = RT + 576;    // bone stage: BT[r*6+m]

    const int i0 = blockIdx.x * 128 + wid * 32;
    const int i  = i0 + lane;
    const bool act = (i < B);
    const int myidx = act ? idxs[act ? i : 0] : 0;

    float px, py, pz;
    {
        size_t pb = (size_t)myidx * 3;
        px = __ldg(pelvis + pb + 0);
        py = __ldg(pelvis + pb + 1);
        pz = __ldg(pelvis + pb + 2);
    }

    const size_t Bs = (size_t)B;
    float* kpo   = out;                 // B*24*3
    float* boneo = out + Bs * 72;       // B*24*3
    float* sktso = out + Bs * 144;      // B*24*16
    float* l2wo  = out + Bs * 528;      // B*24*16
    float* rotso = out + Bs * 912;      // B*24*9

    float Ms[24][12];   // constant-indexed -> registers, liveness-pruned
    float bf[12];       // current 4-joint bone chunk

    // load a 4-joint bone chunk (48B, 16B-aligned) into bf
#define BONES4(j0)                                                              \
    do {                                                                        \
        const float4* bp = reinterpret_cast<const float4*>(                     \
            bones + (size_t)myidx * 72 + (j0) * 3);                             \
        float4 b0 = __ldg(bp + 0), b1 = __ldg(bp + 1), b2 = __ldg(bp + 2);      \
        bf[0]=b0.x; bf[1]=b0.y; bf[2]=b0.z; bf[3]=b0.w;                         \
        bf[4]=b1.x; bf[5]=b1.y; bf[6]=b1.z; bf[7]=b1.w;                         \
        bf[8]=b2.x; bf[9]=b2.y; bf[10]=b2.z; bf[11]=b2.w;                       \
    } while (0)

#define JOINT(j, pj)                                                            \
    do {                                                                        \
        float vx = bf[((j)&3)*3+0], vy = bf[((j)&3)*3+1], vz = bf[((j)&3)*3+2]; \
        float R[9];                                                             \
        axisang_rot(vx, vy, vz, R);                                             \
        {   /* stage rots (elem-contiguous) + bone passthrough */               \
            float* rq = RT + lane * 18 + ((j)&1) * 9;                           \
            rq[0]=R[0]; rq[1]=R[1]; rq[2]=R[2]; rq[3]=R[3]; rq[4]=R[4];         \
            rq[5]=R[5]; rq[6]=R[6]; rq[7]=R[7]; rq[8]=R[8];                     \
            float* bq = BT + lane * 6 + ((j)&1) * 3;                            \
            bq[0]=vx; bq[1]=vy; bq[2]=vz;                                       \
        }                                                                       \
        float tx, ty, tz;                                                       \
        if ((j) == 0) {                                                         \
            tx = __ldg(rest + 0); ty = __ldg(rest + 1); tz = __ldg(rest + 2);   \
        } else {                                                                \
            tx = __ldg(rest + 3 * (j) + 0) - __ldg(rest + 3 * (pj) + 0);        \
            ty = __ldg(rest + 3 * (j) + 1) - __ldg(rest + 3 * (pj) + 1);        \
            tz = __ldg(rest + 3 * (j) + 2) - __ldg(rest + 3 * (pj) + 2);        \
        }                                                                       \
        float* C = Ms[(j)];                                                     \
        if ((j) == 0) {                                                         \
            C[0]=R[0];C[1]=R[1];C[2]=R[2];C[3]=R[3];C[4]=R[4];C[5]=R[5];        \
            C[6]=R[6];C[7]=R[7];C[8]=R[8];C[9]=tx;C[10]=ty;C[11]=tz;            \
        } else {                                                                \
            const float* P = Ms[(pj)];                                          \
            _Pragma("unroll")                                                   \
            for (int r_ = 0; r_ < 3; r_++) {                                    \
                _Pragma("unroll")                                               \
                for (int c_ = 0; c_ < 3; c_++) {                                \
                    C[3*r_+c_] = P[3*r_+0]*R[0+c_] + P[3*r_+1]*R[3+c_]          \
                               + P[3*r_+2]*R[6+c_];                             \
                }                                                               \
                C[9+r_] = P[3*r_+0]*tx + P[3*r_+1]*ty + P[3*r_+2]*tz + P[9+r_]; \
            }                                                                   \
        }                                                                       \
        float twx = C[9] + px, twy = C[10] + py, twz = C[11] + pz;              \
        {   /* stage l2w (stride 144B -> 16B-aligned) */                        \
            float4* l4 = reinterpret_cast<float4*>(                             \
                Lb + lane * LS_STRIDE + ((j)&1)*16);                            \
            l4[0] = make_float4(C[0], C[1], C[2], twx);                         \
            l4[1] = make_float4(C[3], C[4], C[5], twy);                         \
            l4[2] = make_float4(C[6], C[7], C[8], twz);                         \
            l4[3] = make_float4(0.f, 0.f, 0.f, 1.f);                            \
        }                                                                       \
        {   /* rigid inverse: R^T and -R^T t (orthogonal rotation chain) */     \
            float itx = -(C[0]*twx + C[3]*twy + C[6]*twz);                      \
            float ity = -(C[1]*twx + C[4]*twy + C[7]*twz);                      \
            float itz = -(C[2]*twx + C[5]*twy + C[8]*twz);                      \
            float4* s4 = reinterpret_cast<float4*>(                             \
                Sb + lane * LS_STRIDE + ((j)&1)*16);                            \
            s4[0] = make_float4(C[0], C[3], C[6], itx);                         \
            s4[1] = make_float4(C[1], C[4], C[7], ity);                         \
            s4[2] = make_float4(C[2], C[5], C[8], itz);                         \
            s4[3] = make_float4(0.f, 0.f, 0.f, 1.f);                            \
        }                                                                       \
    } while (0)

    // flush 2 staged joints (chunk c = 0..11)
#define FLUSH(c)                                                                \
    do {                                                                        \
        __syncwarp();                                                           \
        _Pragma("unroll")                                                       \
        for (int k = 0; k < 8; ++k) {   /* l2w + skts: 8 x float4 phases */     \
            int q = k * 32 + lane;                                              \
            int r = q >> 3;                                                     \
            int w = (q & 7) * 4;                                                \
            float4 a = *reinterpret_cast<float4*>(Lb + r * LS_STRIDE + w);      \
            float4 b = *reinterpret_cast<float4*>(Sb + r * LS_STRIDE + w);      \
            if (i0 + r < B) {                                                   \
                size_t base = (size_t)(i0 + r) * 384 + (c) * 32 + w;            \
                *reinterpret_cast<float4*>(l2wo + base)  = a;                   \
                *reinterpret_cast<float4*>(sktso + base) = b;                   \
            }                                                                   \
        }                                                                       \
        _Pragma("unroll")                                                       \
        for (int k = 0; k < 18; ++k) {  /* rots: 18 floats/elem */              \
            int q = k * 32 + lane;                                              \
            int r = q / 18;                                                     \
            int m = q - r * 18;                                                 \
            if (i0 + r < B)                                                     \
                rotso[(size_t)(i0 + r) * 216 + (c) * 18 + m] = RT[q];           \
        }                                                                       \
        _Pragma("unroll")                                                       \
        for (int k = 0; k < 6; ++k) {   /* bone: 6 floats/elem */               \
            int q = k * 32 + lane;                                              \
            int r = q / 6;                                                      \
            int m = q - r * 6;                                                  \
            if (i0 + r < B)                                                     \
                boneo[(size_t)(i0 + r) * 72 + (c) * 6 + m] = BT[q];             \
        }                                                                       \
        _Pragma("unroll")                                                       \
        for (int k = 0; k < 6; ++k) {   /* kp from l2w stage (col 3) */         \
            int q = k * 32 + lane;                                              \
            int r = q / 6;                                                      \
            int m = q - r * 6;                                                  \
            int jj = m / 3;                                                     \
            int rw = m - jj * 3;                                                \
            if (i0 + r < B)                                                     \
                kpo[(size_t)(i0 + r) * 72 + (c) * 6 + m] =                      \
                    Lb[r * LS_STRIDE + jj * 16 + rw * 4 + 3];                   \
        }                                                                       \
        __syncwarp();                                                           \
    } while (0)

    // topological order; parent always computed before child
    BONES4(0);
    JOINT(0, 0);   JOINT(1, 0);   FLUSH(0);
    JOINT(2, 0);   JOINT(3, 0);   FLUSH(1);
    BONES4(4);
    JOINT(4, 1);   JOINT(5, 2);   FLUSH(2);
    JOINT(6, 3);   JOINT(7, 4);   FLUSH(3);
    BONES4(8);
    JOINT(8, 5);   JOINT(9, 6);   FLUSH(4);
    JOINT(10, 7);  JOINT(11, 8);  FLUSH(5);
    BONES4(12);
    JOINT(12, 9);  JOINT(13, 9);  FLUSH(6);
    JOINT(14, 9);  JOINT(15, 12); FLUSH(7);
    BONES4(16);
    JOINT(16, 13); JOINT(17, 14); FLUSH(8);
    JOINT(18, 16); JOINT(19, 17); FLUSH(9);
    BONES4(20);
    JOINT(20, 18); JOINT(21, 19); FLUSH(10);
    JOINT(22, 20); JOINT(23, 21); FLUSH(11);

#undef JOINT
#undef FLUSH
#undef BONES4
}

extern "C" void kernel_launch(void* const* d_in, const int* in_sizes, int n_in,
                              void* d_out, int out_size)
{
    const float* pelvis = (const float*)d_in[0];
    const float* bones  = (const float*)d_in[1];
    const float* rest   = (const float*)d_in[2];
    const int*   idxs   = (const int*)d_in[3];
    const int B = in_sizes[3];
    float* out = (float*)d_out;

    const int smem = 4 * WARP_WORDS * 4;  // 49,152 bytes (4 warps/block)
    cudaFuncSetAttribute(fused_kernel,
                         cudaFuncAttributeMaxDynamicSharedMemorySize, smem);

    int blocks = (B + 127) / 128;
    fused_kernel<<<blocks, 128, smem>>>(pelvis, bones, rest, idxs, out, B);
}

// round 14
// speedup vs baseline: 1.2062x; 1.2062x over previous
#include <cuda_runtime.h>

#define FULLMASK 0xffffffffu

__device__ __forceinline__ void axisang_rot(float x, float y, float z, float* __restrict__ R) {
    // reference: theta = sqrt(dot + 1e-8); R = I + s*K + (1-c)*K^2
    // fast-math: MUFU.RSQ / MUFU.SIN / MUFU.COS (error ~2^-21, budget 1e-3)
    float t2 = x * x + y * y + z * z + 1e-8f;
    float inv = rsqrtf(t2);
    float th = t2 * inv;            // sqrt(t2)
    float ax = x * inv, ay = y * inv, az = z * inv;
    float s = __sinf(th);
    float c = __cosf(th);
    float oc = 1.0f - c;
    float xx = ax * ax, yy = ay * ay, zz = az * az;
    float xy = ax * ay, xz = ax * az, yz = ay * az;
    R[0] = 1.0f + oc * (-zz - yy);
    R[1] = -s * az + oc * xy;
    R[2] =  s * ay + oc * xz;
    R[3] =  s * az + oc * xy;
    R[4] = 1.0f + oc * (-zz - xx);
    R[5] = -s * ax + oc * yz;
    R[6] = -s * ay + oc * xz;
    R[7] =  s * ax + oc * yz;
    R[8] = 1.0f + oc * (-yy - xx);
}

// ---------------------------------------------------------------------------
// Heterogeneous kernel: block role by blockIdx (1 chain block : 12 rot blocks
// interleaved) so bandwidth-bound rot blocks co-reside with latency-bound
// chain blocks on every SM and fill their stall slots.
//
// CHAIN role (verbatim R10 layout): per-warp smem L[32*36]|S[32*36]|KP[32*7]
//   = 2528 words; 4 warps -> 40,448 B. Flush every 2 joints, coalesced.
// ROT role: 256 (elem,joint) pairs per block, 2 per thread; stage rt[256*9]+
//   bt[256*3] = 12.3 KB (reuses same dynamic smem); coalesced float4 flush.
// ---------------------------------------------------------------------------
#define LS_STRIDE 36
#define WARP_WORDS (1152 + 1152 + 224)  // 2528

__global__ void __launch_bounds__(128, 4)
hetero_kernel(const float* __restrict__ pelvis, const float* __restrict__ bones,
              const float* __restrict__ rest, const int* __restrict__ idxs,
              float* __restrict__ out, int B, int NC, int NR)
{
    extern __shared__ float sm[];
    const int bid = blockIdx.x;
    const int tid = threadIdx.x;
    const size_t Bs = (size_t)B;

    float* kpo   = out;                 // B*24*3
    float* boneo = out + Bs * 72;       // B*24*3
    float* sktso = out + Bs * 144;      // B*24*16
    float* l2wo  = out + Bs * 528;      // B*24*16
    float* rotso = out + Bs * 912;      // B*24*9

    if (bid % 13 != 0) {
        // ================= ROT role =================
        const int rid = bid - bid / 13 - 1;
        if (rid >= NR) return;
        float* rt = sm;          // 256*9 = 2304 floats
        float* bt = sm + 2304;   // 256*3 = 768 floats

        const long long p0 = (long long)rid * 256;
        const long long NP = (long long)B * 24;

#pragma unroll
        for (int h = 0; h < 2; ++h) {
            int q = h * 128 + tid;                    // staged pair slot
            long long p = p0 + q;
            int ii = (int)(p / 24);
            int jj = (int)(p - (long long)ii * 24);
            const bool act = (p < NP);
            const int idx = act ? idxs[ii] : 0;
            const float* bp = bones + (size_t)idx * 72 + jj * 3;
            float vx = __ldg(bp + 0), vy = __ldg(bp + 1), vz = __ldg(bp + 2);
            bt[q * 3 + 0] = vx; bt[q * 3 + 1] = vy; bt[q * 3 + 2] = vz;
            float R[9];
            axisang_rot(vx, vy, vz, R);
#pragma unroll
            for (int m = 0; m < 9; ++m) rt[q * 9 + m] = R[m];
        }
        __syncthreads();

        const long long rbase = p0 * 9;               // float offset into rots
        const long long rlim  = (long long)B * 216;
#pragma unroll
        for (int k = 0; k < 5; ++k) {                 // 576 float4 / 128 thr
            int q4 = k * 128 + tid;
            if (q4 < 576) {
                long long g = rbase + (long long)q4 * 4;
                if (g < rlim)
                    *reinterpret_cast<float4*>(rotso + g) =
                        reinterpret_cast<float4*>(rt)[q4];
            }
        }
        const long long bbase = p0 * 3;
        const long long blim  = (long long)B * 72;
#pragma unroll
        for (int k = 0; k < 2; ++k) {                 // 192 float4 / 128 thr
            int q4 = k * 128 + tid;
            if (q4 < 192) {
                long long g = bbase + (long long)q4 * 4;
                if (g < blim)
                    *reinterpret_cast<float4*>(boneo + g) =
                        reinterpret_cast<float4*>(bt)[q4];
            }
        }
        return;
    }

    // ================= CHAIN role (verbatim R10) =================
    const int cid = bid / 13;
    if (cid >= NC) return;
    const int lane = tid & 31;
    const int wid  = tid >> 5;
    float* Lb = sm + wid * WARP_WORDS;
    float* Sb = Lb + 1152;
    float* KP = Sb + 1152;

    const int i0 = cid * 128 + wid * 32;
    const int i  = i0 + lane;
    const bool act = (i < B);
    const int myidx = act ? idxs[act ? i : 0] : 0;

    float px, py, pz;
    {
        size_t pb = (size_t)myidx * 3;
        px = __ldg(pelvis + pb + 0);
        py = __ldg(pelvis + pb + 1);
        pz = __ldg(pelvis + pb + 2);
    }

    float Ms[24][12];   // constant-indexed -> registers, liveness-pruned
    float bf[12];       // current 4-joint bone chunk

#define BONES4(j0)                                                              \
    do {                                                                        \
        const float4* bp = reinterpret_cast<const float4*>(                     \
            bones + (size_t)myidx * 72 + (j0) * 3);                             \
        float4 b0 = __ldg(bp + 0), b1 = __ldg(bp + 1), b2 = __ldg(bp + 2);      \
        bf[0]=b0.x; bf[1]=b0.y; bf[2]=b0.z; bf[3]=b0.w;                         \
        bf[4]=b1.x; bf[5]=b1.y; bf[6]=b1.z; bf[7]=b1.w;                         \
        bf[8]=b2.x; bf[9]=b2.y; bf[10]=b2.z; bf[11]=b2.w;                       \
    } while (0)

#define JOINT(j, pj)                                                            \
    do {                                                                        \
        float R[9];                                                             \
        axisang_rot(bf[((j)&3)*3+0], bf[((j)&3)*3+1], bf[((j)&3)*3+2], R);      \
        float tx, ty, tz;                                                       \
        if ((j) == 0) {                                                         \
            tx = __ldg(rest + 0); ty = __ldg(rest + 1); tz = __ldg(rest + 2);   \
        } else {                                                                \
            tx = __ldg(rest + 3 * (j) + 0) - __ldg(rest + 3 * (pj) + 0);        \
            ty = __ldg(rest + 3 * (j) + 1) - __ldg(rest + 3 * (pj) + 1);        \
            tz = __ldg(rest + 3 * (j) + 2) - __ldg(rest + 3 * (pj) + 2);        \
        }                                                                       \
        float* C = Ms[(j)];                                                     \
        if ((j) == 0) {                                                         \
            C[0]=R[0];C[1]=R[1];C[2]=R[2];C[3]=R[3];C[4]=R[4];C[5]=R[5];        \
            C[6]=R[6];C[7]=R[7];C[8]=R[8];C[9]=tx;C[10]=ty;C[11]=tz;            \
        } else {                                                                \
            const float* P = Ms[(pj)];                                          \
            _Pragma("unroll")                                                   \
            for (int r_ = 0; r_ < 3; r_++) {                                    \
                _Pragma("unroll")                                               \
                for (int c_ = 0; c_ < 3; c_++) {                                \
                    C[3*r_+c_] = P[3*r_+0]*R[0+c_] + P[3*r_+1]*R[3+c_]          \
                               + P[3*r_+2]*R[6+c_];                             \
                }                                                               \
                C[9+r_] = P[3*r_+0]*tx + P[3*r_+1]*ty + P[3*r_+2]*tz + P[9+r_]; \
            }                                                                   \
        }                                                                       \
        float twx = C[9] + px, twy = C[10] + py, twz = C[11] + pz;              \
        {   /* stage l2w (stride 144B -> 16B-aligned) */                        \
            float4* l4 = reinterpret_cast<float4*>(                             \
                Lb + lane * LS_STRIDE + ((j)&1)*16);                            \
            l4[0] = make_float4(C[0], C[1], C[2], twx);                         \
            l4[1] = make_float4(C[3], C[4], C[5], twy);                         \
            l4[2] = make_float4(C[6], C[7], C[8], twz);                         \
            l4[3] = make_float4(0.f, 0.f, 0.f, 1.f);                            \
        }                                                                       \
        {   /* stage kp */                                                      \
            float* kq = KP + lane * 7 + ((j)&1) * 3;                            \
            kq[0] = twx; kq[1] = twy; kq[2] = twz;                              \
        }                                                                       \
        {   /* rigid inverse: R^T and -R^T t (orthogonal rotation chain) */     \
            float itx = -(C[0]*twx + C[3]*twy + C[6]*twz);                      \
            float ity = -(C[1]*twx + C[4]*twy + C[7]*twz);                      \
            float itz = -(C[2]*twx + C[5]*twy + C[8]*twz);                      \
            float4* s4 = reinterpret_cast<float4*>(                             \
                Sb + lane * LS_STRIDE + ((j)&1)*16);                            \
            s4[0] = make_float4(C[0], C[3], C[6], itx);                         \
            s4[1] = make_float4(C[1], C[4], C[7], ity);                         \
            s4[2] = make_float4(C[2], C[5], C[8], itz);                         \
            s4[3] = make_float4(0.f, 0.f, 0.f, 1.f);                            \
        }                                                                       \
    } while (0)

#define FLUSH(c)                                                                \
    do {                                                                        \
        __syncwarp();                                                           \
        _Pragma("unroll")                                                       \
        for (int k = 0; k < 8; ++k) {                                           \
            int q = k * 32 + lane;                                              \
            int r = q >> 3;                                                     \
            int w = (q & 7) * 4;                                                \
            float4 a = *reinterpret_cast<float4*>(Lb + r * LS_STRIDE + w);      \
            float4 b = *reinterpret_cast<float4*>(Sb + r * LS_STRIDE + w);      \
            if (i0 + r < B) {                                                   \
                size_t base = (size_t)(i0 + r) * 384 + (c) * 32 + w;            \
                *reinterpret_cast<float4*>(l2wo + base)  = a;                   \
                *reinterpret_cast<float4*>(sktso + base) = b;                   \
            }                                                                   \
        }                                                                       \
        _Pragma("unroll")                                                       \
        for (int k = 0; k < 6; ++k) {                                           \
            int q = k * 32 + lane;                                              \
            int r = q / 6;                                                      \
            int m = q - r * 6;                                                  \
            if (i0 + r < B)                                                     \
                kpo[(size_t)(i0 + r) * 72 + (c) * 6 + m] = KP[r * 7 + m];       \
        }                                                                       \
        __syncwarp();                                                           \
    } while (0)

    // topological order; parent always computed before child
    BONES4(0);
    JOINT(0, 0);   JOINT(1, 0);   FLUSH(0);
    JOINT(2, 0);   JOINT(3, 0);   FLUSH(1);
    BONES4(4);
    JOINT(4, 1);   JOINT(5, 2);   FLUSH(2);
    JOINT(6, 3);   JOINT(7, 4);   FLUSH(3);
    BONES4(8);
    JOINT(8, 5);   JOINT(9, 6);   FLUSH(4);
    JOINT(10, 7);  JOINT(11, 8);  FLUSH(5);
    BONES4(12);
    JOINT(12, 9);  JOINT(13, 9);  FLUSH(6);
    JOINT(14, 9);  JOINT(15, 12); FLUSH(7);
    BONES4(16);
    JOINT(16, 13); JOINT(17, 14); FLUSH(8);
    JOINT(18, 16); JOINT(19, 17); FLUSH(9);
    BONES4(20);
    JOINT(20, 18); JOINT(21, 19); FLUSH(10);
    JOINT(22, 20); JOINT(23, 21); FLUSH(11);

#undef JOINT
#undef FLUSH
#undef BONES4
}

extern "C" void kernel_launch(void* const* d_in, const int* in_sizes, int n_in,
                              void* d_out, int out_size)
{
    const float* pelvis = (const float*)d_in[0];
    const float* bones  = (const float*)d_in[1];
    const float* rest   = (const float*)d_in[2];
    const int*   idxs   = (const int*)d_in[3];
    const int B = in_sizes[3];
    float* out = (float*)d_out;

    const int NC = (B + 127) / 128;                       // chain blocks
    const long long pairs = (long long)B * 24;
    const int NR = (int)((pairs + 255) / 256);            // rot blocks
    int per = NC > (NR + 11) / 12 ? NC : (NR + 11) / 12;  // interleave groups
    int grid = 13 * per;

    const int smem = 4 * WARP_WORDS * 4;                  // 40,448 bytes
    cudaFuncSetAttribute(hetero_kernel,
                         cudaFuncAttributeMaxDynamicSharedMemorySize, smem);

    hetero_kernel<<<grid, 128, smem>>>(pelvis, bones, rest, idxs, out, B, NC, NR);
}

// round 15
// speedup vs baseline: 1.5488x; 1.2841x over previous
#include <cuda_runtime.h>

#define FULLMASK 0xffffffffu

__device__ __forceinline__ void axisang_rot(float x, float y, float z, float* __restrict__ R) {
    // reference: theta = sqrt(dot + 1e-8); R = I + s*K + (1-c)*K^2
    // fast-math: MUFU.RSQ / MUFU.SIN / MUFU.COS (error ~2^-21, budget 1e-3)
    float t2 = x * x + y * y + z * z + 1e-8f;
    float inv = rsqrtf(t2);
    float th = t2 * inv;            // sqrt(t2)
    float ax = x * inv, ay = y * inv, az = z * inv;
    float s = __sinf(th);
    float c = __cosf(th);
    float oc = 1.0f - c;
    float xx = ax * ax, yy = ay * ay, zz = az * az;
    float xy = ax * ay, xz = ax * az, yz = ay * az;
    R[0] = 1.0f + oc * (-zz - yy);
    R[1] = -s * az + oc * xy;
    R[2] =  s * ay + oc * xz;
    R[3] =  s * az + oc * xy;
    R[4] = 1.0f + oc * (-zz - xx);
    R[5] = -s * ax + oc * yz;
    R[6] = -s * ay + oc * xz;
    R[7] =  s * ax + oc * yz;
    R[8] = 1.0f + oc * (-yy - xx);
}

// ---------------------------------------------------------------------------
// Single kernel, two sequential phases (register pressure = max, not sum):
// Phase A (verbatim R10 chain): l2ws, skts, kp via staged coalesced stores.
// Phase B (appended): rots + bone for the SAME 128 elements; bones rows are
//   L2-hot from phase A; rotations recomputed (MUFU-cheap), staged in the
//   now-free Lb/Sb smem, flushed as coalesced float4 stores.
// Per-warp smem: L[32*36] | S[32*36] | KP[32*7] = 2528 words (10.1 KB).
// ---------------------------------------------------------------------------
#define LS_STRIDE 36
#define WARP_WORDS (1152 + 1152 + 224)  // 2528

__global__ void __launch_bounds__(128)
chain_kernel(const float* __restrict__ pelvis, const float* __restrict__ bones,
             const float* __restrict__ rest, const int* __restrict__ idxs,
             float* __restrict__ out, int B)
{
    extern __shared__ float sm[];
    const int lane = threadIdx.x & 31;
    const int wid  = threadIdx.x >> 5;
    float* Lb = sm + wid * WARP_WORDS;
    float* Sb = Lb + 1152;
    float* KP = Sb + 1152;

    const int i0 = blockIdx.x * 128 + wid * 32;
    const int i  = i0 + lane;
    const bool act = (i < B);
    const int myidx = act ? idxs[act ? i : 0] : 0;

    float px, py, pz;
    {
        size_t pb = (size_t)myidx * 3;
        px = __ldg(pelvis + pb + 0);
        py = __ldg(pelvis + pb + 1);
        pz = __ldg(pelvis + pb + 2);
    }

    const size_t Bs = (size_t)B;
    float* kpo   = out;                 // B*24*3
    float* boneo = out + Bs * 72;       // B*24*3
    float* sktso = out + Bs * 144;      // B*24*16
    float* l2wo  = out + Bs * 528;      // B*24*16
    float* rotso = out + Bs * 912;      // B*24*9

    float Ms[24][12];   // constant-indexed -> registers, liveness-pruned
    float bf[12];       // current 4-joint bone chunk

    // load a 4-joint bone chunk (48B, 16B-aligned) into bf
#define BONES4(j0)                                                              \
    do {                                                                        \
        const float4* bp = reinterpret_cast<const float4*>(                     \
            bones + (size_t)myidx * 72 + (j0) * 3);                             \
        float4 b0 = __ldg(bp + 0), b1 = __ldg(bp + 1), b2 = __ldg(bp + 2);      \
        bf[0]=b0.x; bf[1]=b0.y; bf[2]=b0.z; bf[3]=b0.w;                         \
        bf[4]=b1.x; bf[5]=b1.y; bf[6]=b1.z; bf[7]=b1.w;                         \
        bf[8]=b2.x; bf[9]=b2.y; bf[10]=b2.z; bf[11]=b2.w;                       \
    } while (0)

#define JOINT(j, pj)                                                            \
    do {                                                                        \
        float R[9];                                                             \
        axisang_rot(bf[((j)&3)*3+0], bf[((j)&3)*3+1], bf[((j)&3)*3+2], R);      \
        float tx, ty, tz;                                                       \
        if ((j) == 0) {                                                         \
            tx = __ldg(rest + 0); ty = __ldg(rest + 1); tz = __ldg(rest + 2);   \
        } else {                                                                \
            tx = __ldg(rest + 3 * (j) + 0) - __ldg(rest + 3 * (pj) + 0);        \
            ty = __ldg(rest + 3 * (j) + 1) - __ldg(rest + 3 * (pj) + 1);        \
            tz = __ldg(rest + 3 * (j) + 2) - __ldg(rest + 3 * (pj) + 2);        \
        }                                                                       \
        float* C = Ms[(j)];                                                     \
        if ((j) == 0) {                                                         \
            C[0]=R[0];C[1]=R[1];C[2]=R[2];C[3]=R[3];C[4]=R[4];C[5]=R[5];        \
            C[6]=R[6];C[7]=R[7];C[8]=R[8];C[9]=tx;C[10]=ty;C[11]=tz;            \
        } else {                                                                \
            const float* P = Ms[(pj)];                                          \
            _Pragma("unroll")                                                   \
            for (int r_ = 0; r_ < 3; r_++) {                                    \
                _Pragma("unroll")                                               \
                for (int c_ = 0; c_ < 3; c_++) {                                \
                    C[3*r_+c_] = P[3*r_+0]*R[0+c_] + P[3*r_+1]*R[3+c_]          \
                               + P[3*r_+2]*R[6+c_];                             \
                }                                                               \
                C[9+r_] = P[3*r_+0]*tx + P[3*r_+1]*ty + P[3*r_+2]*tz + P[9+r_]; \
            }                                                                   \
        }                                                                       \
        float twx = C[9] + px, twy = C[10] + py, twz = C[11] + pz;              \
        {   /* stage l2w (stride 144B -> 16B-aligned) */                        \
            float4* l4 = reinterpret_cast<float4*>(                             \
                Lb + lane * LS_STRIDE + ((j)&1)*16);                            \
            l4[0] = make_float4(C[0], C[1], C[2], twx);                         \
            l4[1] = make_float4(C[3], C[4], C[5], twy);                         \
            l4[2] = make_float4(C[6], C[7], C[8], twz);                         \
            l4[3] = make_float4(0.f, 0.f, 0.f, 1.f);                            \
        }                                                                       \
        {   /* stage kp */                                                      \
            float* kq = KP + lane * 7 + ((j)&1) * 3;                            \
            kq[0] = twx; kq[1] = twy; kq[2] = twz;                              \
        }                                                                       \
        {   /* rigid inverse: R^T and -R^T t (orthogonal rotation chain) */     \
            float itx = -(C[0]*twx + C[3]*twy + C[6]*twz);                      \
            float ity = -(C[1]*twx + C[4]*twy + C[7]*twz);                      \
            float itz = -(C[2]*twx + C[5]*twy + C[8]*twz);                      \
            float4* s4 = reinterpret_cast<float4*>(                             \
                Sb + lane * LS_STRIDE + ((j)&1)*16);                            \
            s4[0] = make_float4(C[0], C[3], C[6], itx);                         \
            s4[1] = make_float4(C[1], C[4], C[7], ity);                         \
            s4[2] = make_float4(C[2], C[5], C[8], itz);                         \
            s4[3] = make_float4(0.f, 0.f, 0.f, 1.f);                            \
        }                                                                       \
    } while (0)

    // flush 2 staged joints (chunk c = 0..11): 32 floats/elem -> 8 float4 iters
#define FLUSH(c)                                                                \
    do {                                                                        \
        __syncwarp();                                                           \
        _Pragma("unroll")                                                       \
        for (int k = 0; k < 8; ++k) {                                           \
            int q = k * 32 + lane;                                              \
            int r = q >> 3;                                                     \
            int w = (q & 7) * 4;                                                \
            float4 a = *reinterpret_cast<float4*>(Lb + r * LS_STRIDE + w);      \
            float4 b = *reinterpret_cast<float4*>(Sb + r * LS_STRIDE + w);      \
            if (i0 + r < B) {                                                   \
                size_t base = (size_t)(i0 + r) * 384 + (c) * 32 + w;            \
                *reinterpret_cast<float4*>(l2wo + base)  = a;                   \
                *reinterpret_cast<float4*>(sktso + base) = b;                   \
            }                                                                   \
        }                                                                       \
        _Pragma("unroll")                                                       \
        for (int k = 0; k < 6; ++k) {                                           \
            int q = k * 32 + lane;                                              \
            int r = q / 6;                                                      \
            int m = q - r * 6;                                                  \
            if (i0 + r < B)                                                     \
                kpo[(size_t)(i0 + r) * 72 + (c) * 6 + m] = KP[r * 7 + m];       \
        }                                                                       \
        __syncwarp();                                                           \
    } while (0)

    // ===================== Phase A: chain (verbatim R10) =====================
    BONES4(0);
    JOINT(0, 0);   JOINT(1, 0);   FLUSH(0);
    JOINT(2, 0);   JOINT(3, 0);   FLUSH(1);
    BONES4(4);
    JOINT(4, 1);   JOINT(5, 2);   FLUSH(2);
    JOINT(6, 3);   JOINT(7, 4);   FLUSH(3);
    BONES4(8);
    JOINT(8, 5);   JOINT(9, 6);   FLUSH(4);
    JOINT(10, 7);  JOINT(11, 8);  FLUSH(5);
    BONES4(12);
    JOINT(12, 9);  JOINT(13, 9);  FLUSH(6);
    JOINT(14, 9);  JOINT(15, 12); FLUSH(7);
    BONES4(16);
    JOINT(16, 13); JOINT(17, 14); FLUSH(8);
    JOINT(18, 16); JOINT(19, 17); FLUSH(9);
    BONES4(20);
    JOINT(20, 18); JOINT(21, 19); FLUSH(10);
    JOINT(22, 20); JOINT(23, 21); FLUSH(11);

#undef JOINT
#undef FLUSH
#undef BONES4

    // ===================== Phase B: rots + bone passthrough ==================
    // Reuse Lb (as RT: 36 words/elem) and Sb (as BT: 12 words/elem).
    // Rolled chunk loop (6 x 4 joints) keeps code small and regs low.
    {
        float* RT = Lb;     // 32*36 = 1152 words
        float* BT = Sb;     // 32*12 = 384 words (of 1152)

        for (int c = 0; c < 6; ++c) {          // intentionally NOT unrolled
            // reload this 4-joint bone chunk (L2-hot from phase A)
            const float4* bp = reinterpret_cast<const float4*>(
                bones + (size_t)myidx * 72 + c * 12);
            float4 b0 = __ldg(bp + 0), b1 = __ldg(bp + 1), b2 = __ldg(bp + 2);
            float bb[12];
            bb[0]=b0.x; bb[1]=b0.y; bb[2]=b0.z; bb[3]=b0.w;
            bb[4]=b1.x; bb[5]=b1.y; bb[6]=b1.z; bb[7]=b1.w;
            bb[8]=b2.x; bb[9]=b2.y; bb[10]=b2.z; bb[11]=b2.w;

#pragma unroll
            for (int k = 0; k < 4; ++k) {
                float R[9];
                axisang_rot(bb[k*3+0], bb[k*3+1], bb[k*3+2], R);
                float* rq = RT + lane * 36 + k * 9;
#pragma unroll
                for (int m = 0; m < 9; ++m) rq[m] = R[m];
                float* bq = BT + lane * 12 + k * 3;
                bq[0] = bb[k*3+0]; bq[1] = bb[k*3+1]; bq[2] = bb[k*3+2];
            }
            __syncwarp();

            // flush rots: 36 floats/elem = 9 float4 x 32 elems = 288 float4
#pragma unroll
            for (int k = 0; k < 9; ++k) {
                int q = k * 32 + lane;
                int r = q / 9;
                int w = q - r * 9;
                if (i0 + r < B)
                    *reinterpret_cast<float4*>(
                        rotso + (size_t)(i0 + r) * 216 + c * 36 + w * 4) =
                        *reinterpret_cast<float4*>(RT + r * 36 + w * 4);
            }
            // flush bone: 12 floats/elem = 3 float4 x 32 elems = 96 float4
#pragma unroll
            for (int k = 0; k < 3; ++k) {
                int q = k * 32 + lane;
                int r = q / 3;
                int m = q - r * 3;
                if (i0 + r < B)
                    *reinterpret_cast<float4*>(
                        boneo + (size_t)(i0 + r) * 72 + c * 12 + m * 4) =
                        *reinterpret_cast<float4*>(BT + r * 12 + m * 4);
            }
            __syncwarp();
        }
    }
}

extern "C" void kernel_launch(void* const* d_in, const int* in_sizes, int n_in,
                              void* d_out, int out_size)
{
    const float* pelvis = (const float*)d_in[0];
    const float* bones  = (const float*)d_in[1];
    const float* rest   = (const float*)d_in[2];
    const int*   idxs   = (const int*)d_in[3];
    const int B = in_sizes[3];
    float* out = (float*)d_out;

    const int smem = 4 * WARP_WORDS * 4;  // 40,448 bytes
    cudaFuncSetAttribute(chain_kernel,
                         cudaFuncAttributeMaxDynamicSharedMemorySize, smem);

    int blocks = (B + 127) / 128;
    chain_kernel<<<blocks, 128, smem>>>(pelvis, bones, rest, idxs, out, B);
}